// round 3
// baseline (speedup 1.0000x reference)
#include <cuda_runtime.h>
#include <cuda_bf16.h>

// Problem constants (from reference)
#define MAXN 50000
#define MAXE 800000
#define MAXG 2500

// ---- device scratch (no allocations allowed) ----
__device__ __align__(16) float g_h0[MAXN * 16];   // padded concat(x,pos): cols 14,15 = 0
__device__ __align__(16) float g_z1[MAXN * 16];   // h0 + agg1
__device__ __align__(16) float g_h1[MAXN * 64];   // conv1 output
__device__ __align__(16) float g_z2[MAXN * 64];   // h1 + agg2
__device__ __align__(16) float g_psum[MAXG * 64]; // pooled sums
__device__ float g_pcnt[MAXG];                    // graph node counts
__device__ int2  g_edge[MAXE];                    // (src,dst) as int32
__device__ int   g_batch[MAXN];                   // graph id per node (int32)
__device__ int   g_is64;                          // 1 if index buffers are int64

__device__ __forceinline__ void red_add_v4(float4* addr, float4 v) {
    asm volatile("red.global.add.v4.f32 [%0], {%1,%2,%3,%4};"
                 :: "l"(addr), "f"(v.x), "f"(v.y), "f"(v.z), "f"(v.w)
                 : "memory");
}

// ---- dtype detection: int64 index buffers have all-zero high words ----
__global__ void detect_kernel(const unsigned int* __restrict__ ei_raw, int E) {
    if (blockIdx.x == 0 && threadIdx.x == 0) {
        int is64 = 1;
        for (int s = 0; s < 1024; s++) {
            long i = (long)s * E / 1024;          // element index, i < E
            if (ei_raw[2 * i + 1] != 0u) { is64 = 0; break; }
        }
        g_is64 = is64;
    }
}

// ---- build padded h0, init z1 = h0, convert edges+batch to int32 ----
__global__ void init_kernel(const float* __restrict__ x, const float* __restrict__ pos,
                            const void* __restrict__ ei, const void* __restrict__ batch,
                            int n, int E) {
    int i = blockIdx.x * blockDim.x + threadIdx.x;
    int is64 = g_is64;
    if (i < n * 16) {
        int node = i >> 4, c = i & 15;
        float v = 0.f;
        if (c < 11)       v = x[node * 11 + c];
        else if (c < 14)  v = pos[node * 3 + (c - 11)];
        g_h0[i] = v;
        g_z1[i] = v;
    }
    if (i < E) {
        int s, d;
        if (is64) {
            const long long* p = (const long long*)ei;
            s = (int)p[i]; d = (int)p[E + i];
        } else {
            const int* p = (const int*)ei;
            s = p[i]; d = p[E + i];
        }
        g_edge[i] = make_int2(s, d);
    }
    if (i < n) {
        g_batch[i] = is64 ? (int)((const long long*)batch)[i]
                          : ((const int*)batch)[i];
    }
}

// ---- scatter: z[dst] += h[src], vectorized float4, L2 atomics ----
template<int LOGC4, bool FIRST>
__global__ void scatter_kernel(int E) {
    const float4* __restrict__ h = FIRST ? (const float4*)g_h0 : (const float4*)g_h1;
    float4* zz = FIRST ? (float4*)g_z1 : (float4*)g_z2;
    int idx = blockIdx.x * blockDim.x + threadIdx.x;
    int e = idx >> LOGC4;
    if (e >= E) return;
    int c = idx & ((1 << LOGC4) - 1);
    int2 ed = g_edge[e];
    float4 v = h[((long)ed.x << LOGC4) + c];
    red_add_v4(zz + (((long)ed.y << LOGC4) + c), v);
}

// ---- fused GIN MLP: out = relu-ish( relu(z@Wa+ba) @ Wb + bb ) ----
// Activations read directly from global (L1-resident per-warp rows).
// PHASE 1: reads g_z1 [n,16], writes g_h1 AND g_z2 (copy for next conv init)
// PHASE 2: reads g_z2 [n,64], relu + red-adds rows into g_psum[batch[node]]
template<int DIN, int PHASE>
__launch_bounds__(128)
__global__ void mlp_kernel(const float* __restrict__ Wa, const float* __restrict__ ba,
                           const float* __restrict__ Wb, const float* __restrict__ bb,
                           int wa_rows, int n) {
    __shared__ __align__(16) float sWa[DIN * 64];
    __shared__ __align__(16) float sWb[64 * 64];
    __shared__ float sb[128];          // ba | bb

    int tid = threadIdx.x;
    for (int i = tid; i < DIN * 64; i += 128) sWa[i] = (i < wa_rows * 64) ? Wa[i] : 0.f;
    for (int i = tid; i < 64 * 64; i += 128)  sWb[i] = Wb[i];
    if (tid < 64) sb[tid] = ba[tid]; else sb[tid] = bb[tid - 64];
    __syncthreads();

    int node = blockIdx.x * 128 + tid;
    if (node >= n) return;

    const float4* __restrict__ zr4 = (const float4*)
        (((PHASE == 1) ? g_z1 : g_z2) + (size_t)node * DIN);

    float t[64];

    // first GEMM: t = relu(z @ Wa + ba)
    #pragma unroll
    for (int jt = 0; jt < 2; jt++) {
        float acc[32];
        #pragma unroll
        for (int j = 0; j < 32; j++) acc[j] = sb[jt * 32 + j];
        #pragma unroll
        for (int k4 = 0; k4 < DIN / 4; k4++) {
            float4 zv = zr4[k4];
            #pragma unroll
            for (int kk = 0; kk < 4; kk++) {
                float zk = (&zv.x)[kk];
                const float4* w = reinterpret_cast<const float4*>(
                    &sWa[(k4 * 4 + kk) * 64 + jt * 32]);
                #pragma unroll
                for (int j = 0; j < 8; j++) {
                    float4 wv = w[j];
                    acc[j * 4 + 0] += zk * wv.x;
                    acc[j * 4 + 1] += zk * wv.y;
                    acc[j * 4 + 2] += zk * wv.z;
                    acc[j * 4 + 3] += zk * wv.w;
                }
            }
        }
        #pragma unroll
        for (int j = 0; j < 32; j++) t[jt * 32 + j] = fmaxf(acc[j], 0.f);
    }

    // second GEMM: out = relu(t @ Wb + bb), epilogue per phase
    #pragma unroll
    for (int jt = 0; jt < 2; jt++) {
        float acc[32];
        #pragma unroll
        for (int j = 0; j < 32; j++) acc[j] = sb[64 + jt * 32 + j];
        #pragma unroll
        for (int k = 0; k < 64; k++) {
            float tk = t[k];
            const float4* w = reinterpret_cast<const float4*>(&sWb[k * 64 + jt * 32]);
            #pragma unroll
            for (int j = 0; j < 8; j++) {
                float4 wv = w[j];
                acc[j * 4 + 0] += tk * wv.x;
                acc[j * 4 + 1] += tk * wv.y;
                acc[j * 4 + 2] += tk * wv.z;
                acc[j * 4 + 3] += tk * wv.w;
            }
        }
        if (PHASE == 1) {
            float4* o1 = (float4*)&g_h1[(size_t)node * 64 + jt * 32];
            float4* o2 = (float4*)&g_z2[(size_t)node * 64 + jt * 32];
            #pragma unroll
            for (int j = 0; j < 8; j++) {
                float4 v = make_float4(fmaxf(acc[j*4+0],0.f), fmaxf(acc[j*4+1],0.f),
                                       fmaxf(acc[j*4+2],0.f), fmaxf(acc[j*4+3],0.f));
                o1[j] = v; o2[j] = v;
            }
        } else {
            int g = g_batch[node];
            float4* ps = (float4*)&g_psum[(size_t)g * 64 + jt * 32];
            #pragma unroll
            for (int j = 0; j < 8; j++) {
                float4 v = make_float4(fmaxf(acc[j*4+0],0.f), fmaxf(acc[j*4+1],0.f),
                                       fmaxf(acc[j*4+2],0.f), fmaxf(acc[j*4+3],0.f));
                red_add_v4(&ps[j], v);
            }
        }
    }
}

// ---- pooling support ----
__global__ void pool_zero(int G) {
    int i = blockIdx.x * blockDim.x + threadIdx.x;
    if (i < G * 64) g_psum[i] = 0.f;
    if (i < G)      g_pcnt[i] = 0.f;
}

__global__ void pool_count(int n) {
    int i = blockIdx.x * blockDim.x + threadIdx.x;
    if (i < n) atomicAdd(&g_pcnt[g_batch[i]], 1.f);
}

// ---- final: out[g] = dot(psum[g], Wlin) / max(cnt,1) + blin ----
__global__ void final_kernel(const float* __restrict__ Wlin, const float* __restrict__ blin,
                             float* __restrict__ out, int G) {
    int gw = (blockIdx.x * blockDim.x + threadIdx.x) >> 5;
    int lane = threadIdx.x & 31;
    if (gw >= G) return;
    float s = g_psum[gw * 64 + lane] * Wlin[lane]
            + g_psum[gw * 64 + 32 + lane] * Wlin[32 + lane];
    #pragma unroll
    for (int o = 16; o; o >>= 1) s += __shfl_down_sync(0xffffffffu, s, o);
    if (lane == 0) out[gw] = s / fmaxf(g_pcnt[gw], 1.f) + blin[0];
}

extern "C" void kernel_launch(void* const* d_in, const int* in_sizes, int n_in,
                              void* d_out, int out_size) {
    const float* x     = (const float*)d_in[0];
    const float* pos   = (const float*)d_in[1];
    const void*  eidx  = d_in[2];
    const void*  batch = d_in[3];
    const float* W1a = (const float*)d_in[4];
    const float* b1a = (const float*)d_in[5];
    const float* W1b = (const float*)d_in[6];
    const float* b1b = (const float*)d_in[7];
    const float* W2a = (const float*)d_in[8];
    const float* b2a = (const float*)d_in[9];
    const float* W2b = (const float*)d_in[10];
    const float* b2b = (const float*)d_in[11];
    const float* Wlin = (const float*)d_in[12];
    const float* blin = (const float*)d_in[13];
    float* out = (float*)d_out;

    int n = in_sizes[3];          // nodes (batch length)
    int E = in_sizes[2] / 2;      // edges
    int G = out_size;             // graphs

    detect_kernel<<<1, 32>>>((const unsigned int*)eidx, E);

    int initN = (n * 16 > E) ? n * 16 : E;
    init_kernel<<<(initN + 255) / 256, 256>>>(x, pos, eidx, batch, n, E);

    // conv1: scatter h0 into z1 (4 float4 chunks/row)
    scatter_kernel<2, true><<<(E * 4 + 255) / 256, 256>>>(E);

    // conv1 MLP: z1[n,16] -> h1 (+ copy into z2)
    mlp_kernel<16, 1><<<(n + 127) / 128, 128>>>(W1a, b1a, W1b, b1b, 14, n);

    // pooling buffers: zero + counts (independent of h values)
    pool_zero<<<(G * 64 + 255) / 256, 256>>>(G);
    pool_count<<<(n + 255) / 256, 256>>>(n);

    // conv2: scatter h1 into z2 (16 float4 chunks/row)
    scatter_kernel<4, false><<<(E * 16 + 255) / 256, 256>>>(E);

    // conv2 MLP: z2[n,64] -> relu -> pooled sums (fused)
    mlp_kernel<64, 2><<<(n + 127) / 128, 128>>>(W2a, b2a, W2b, b2b, 64, n);

    // final linear per graph
    final_kernel<<<(G * 32 + 255) / 256, 256>>>(Wlin, blin, out, G);
}

// round 4
// speedup vs baseline: 1.0180x; 1.0180x over previous
#include <cuda_runtime.h>
#include <cuda_bf16.h>

#define MAXN 50000
#define MAXE 800000
#define MAXG 2500

typedef unsigned long long u64;

// ---- device scratch (no allocations allowed) ----
__device__ __align__(16) float g_h0[MAXN * 16];   // padded concat(x,pos)
__device__ __align__(16) float g_z1[MAXN * 16];   // h0 + agg1
__device__ __align__(16) float g_h1[MAXN * 64];   // conv1 output
__device__ __align__(16) float g_z2[MAXN * 64];   // agg2 only (zero-init)
__device__ __align__(16) float g_psum[MAXG * 64]; // pooled sums
__device__ float g_pcnt[MAXG];
__device__ int2  g_edge[MAXE];
__device__ int   g_batch[MAXN];
__device__ int   g_is64;

__device__ __forceinline__ void red_add_v4(float4* addr, float4 v) {
    asm volatile("red.global.add.v4.f32 [%0], {%1,%2,%3,%4};"
                 :: "l"(addr), "f"(v.x), "f"(v.y), "f"(v.z), "f"(v.w)
                 : "memory");
}
__device__ __forceinline__ u64 dup2(float a) {
    u64 r; asm("mov.b64 %0, {%1, %1};" : "=l"(r) : "r"(__float_as_uint(a)));
    return r;
}
__device__ __forceinline__ void ffma2(u64& d, u64 a, u64 b) {
    asm("fma.rn.f32x2 %0, %1, %2, %0;" : "+l"(d) : "l"(a), "l"(b));
}
__device__ __forceinline__ float2 unpack2(u64 v) {
    unsigned lo, hi; asm("mov.b64 {%0, %1}, %2;" : "=r"(lo), "=r"(hi) : "l"(v));
    return make_float2(__uint_as_float(lo), __uint_as_float(hi));
}

// ---- dtype detection: int64 index buffers have all-zero high words ----
__global__ void detect_kernel(const unsigned int* __restrict__ ei_raw, int E) {
    if (blockIdx.x == 0 && threadIdx.x == 0) {
        int is64 = 1;
        for (int s = 0; s < 1024; s++) {
            long i = (long)s * E / 1024;
            if (ei_raw[2 * i + 1] != 0u) { is64 = 0; break; }
        }
        g_is64 = is64;
    }
}

// ---- init: padded h0, z1=h0, z2=0, psum/pcnt=0, edges+batch -> int32 ----
__global__ void init_kernel(const float* __restrict__ x, const float* __restrict__ pos,
                            const void* __restrict__ ei, const void* __restrict__ batch,
                            int n, int E, int G) {
    int i = blockIdx.x * blockDim.x + threadIdx.x;
    int is64 = g_is64;
    if (i < n * 16) {
        int node = i >> 4, c = i & 15;
        float v = 0.f;
        if (c < 11)       v = x[node * 11 + c];
        else if (c < 14)  v = pos[node * 3 + (c - 11)];
        g_h0[i] = v;
        g_z1[i] = v;
    }
    if (i < n * 64) g_z2[i] = 0.f;
    if (i < E) {
        int s, d;
        if (is64) {
            const long long* p = (const long long*)ei;
            s = (int)p[i]; d = (int)p[E + i];
        } else {
            const int* p = (const int*)ei;
            s = p[i]; d = p[E + i];
        }
        g_edge[i] = make_int2(s, d);
    }
    if (i < n) {
        g_batch[i] = is64 ? (int)((const long long*)batch)[i]
                          : ((const int*)batch)[i];
    }
    if (i < G * 64) g_psum[i] = 0.f;
    if (i < G)      g_pcnt[i] = 0.f;
}

// ---- scatter: z[dst] += h[src], float4 lanes, L2 red atomics ----
template<int LOGC4, bool FIRST>
__global__ void scatter_kernel(int E) {
    const float4* __restrict__ h = FIRST ? (const float4*)g_h0 : (const float4*)g_h1;
    float4* zz = FIRST ? (float4*)g_z1 : (float4*)g_z2;
    int idx = blockIdx.x * blockDim.x + threadIdx.x;
    int e = idx >> LOGC4;
    if (e >= E) return;
    int c = idx & ((1 << LOGC4) - 1);
    int2 ed = g_edge[e];
    float4 v = h[((long)ed.x << LOGC4) + c];
    red_add_v4(zz + (((long)ed.y << LOGC4) + c), v);
}

// ---- fused GIN MLP with packed f32x2 math ----
// PHASE 1: z = g_z1 [n,16]  -> writes g_h1
// PHASE 2: z = g_h1 + g_z2  -> relu + red-add into g_psum[batch[node]]
template<int DIN, int PHASE>
__launch_bounds__(128, 4)
__global__ void mlp_kernel(const float* __restrict__ Wa, const float* __restrict__ ba,
                           const float* __restrict__ Wb, const float* __restrict__ bb,
                           int wa_rows, int n) {
    __shared__ __align__(16) float sWa[DIN * 64];
    __shared__ __align__(16) float sWb[64 * 64];
    __shared__ __align__(16) float sb[128];      // ba | bb

    int tid = threadIdx.x;
    for (int i = tid; i < DIN * 64; i += 128) sWa[i] = (i < wa_rows * 64) ? Wa[i] : 0.f;
    for (int i = tid; i < 64 * 64; i += 128)  sWb[i] = Wb[i];
    if (tid < 64) sb[tid] = ba[tid]; else sb[tid] = bb[tid - 64];
    __syncthreads();

    int node = blockIdx.x * 128 + tid;
    if (node >= n) return;

    // ---- first GEMM: acc2[32] = all 64 outputs as packed pairs ----
    u64 acc2[32];
    const u64* sbp = (const u64*)sb;
    #pragma unroll
    for (int j = 0; j < 32; j++) acc2[j] = sbp[j];

    #pragma unroll
    for (int k4 = 0; k4 < DIN / 4; k4++) {
        float4 zv;
        if (PHASE == 1) {
            zv = ((const float4*)(g_z1 + (size_t)node * DIN))[k4];
        } else {
            float4 a = ((const float4*)(g_h1 + (size_t)node * 64))[k4];
            float4 b = ((const float4*)(g_z2 + (size_t)node * 64))[k4];
            zv = make_float4(a.x + b.x, a.y + b.y, a.z + b.z, a.w + b.w);
        }
        #pragma unroll
        for (int kk = 0; kk < 4; kk++) {
            u64 zk2 = dup2((&zv.x)[kk]);
            const u64* w = (const u64*)&sWa[(k4 * 4 + kk) * 64];
            #pragma unroll
            for (int j = 0; j < 32; j++) ffma2(acc2[j], zk2, w[j]);
        }
    }

    float t[64];
    #pragma unroll
    for (int j = 0; j < 32; j++) {
        float2 p = unpack2(acc2[j]);
        t[2 * j]     = fmaxf(p.x, 0.f);
        t[2 * j + 1] = fmaxf(p.y, 0.f);
    }

    // ---- second GEMM: 2 tiles of 32 outputs (16 packed pairs) ----
    #pragma unroll
    for (int jt = 0; jt < 2; jt++) {
        u64 a2[16];
        #pragma unroll
        for (int j = 0; j < 16; j++) a2[j] = sbp[32 + jt * 16 + j];
        #pragma unroll
        for (int k = 0; k < 64; k++) {
            u64 tk2 = dup2(t[k]);
            const u64* w = (const u64*)&sWb[k * 64 + jt * 32];
            #pragma unroll
            for (int j = 0; j < 16; j++) ffma2(a2[j], tk2, w[j]);
        }
        if (PHASE == 1) {
            float4* o1 = (float4*)&g_h1[(size_t)node * 64 + jt * 32];
            #pragma unroll
            for (int j = 0; j < 8; j++) {
                float2 p0 = unpack2(a2[2 * j]);
                float2 p1 = unpack2(a2[2 * j + 1]);
                o1[j] = make_float4(fmaxf(p0.x, 0.f), fmaxf(p0.y, 0.f),
                                    fmaxf(p1.x, 0.f), fmaxf(p1.y, 0.f));
            }
        } else {
            int g = g_batch[node];
            float4* ps = (float4*)&g_psum[(size_t)g * 64 + jt * 32];
            #pragma unroll
            for (int j = 0; j < 8; j++) {
                float2 p0 = unpack2(a2[2 * j]);
                float2 p1 = unpack2(a2[2 * j + 1]);
                red_add_v4(&ps[j], make_float4(fmaxf(p0.x, 0.f), fmaxf(p0.y, 0.f),
                                               fmaxf(p1.x, 0.f), fmaxf(p1.y, 0.f)));
            }
        }
    }
}

// ---- pooling counts ----
__global__ void pool_count(int n) {
    int i = blockIdx.x * blockDim.x + threadIdx.x;
    if (i < n) atomicAdd(&g_pcnt[g_batch[i]], 1.f);
}

// ---- final: out[g] = dot(psum[g], Wlin) / max(cnt,1) + blin ----
__global__ void final_kernel(const float* __restrict__ Wlin, const float* __restrict__ blin,
                             float* __restrict__ out, int G) {
    int gw = (blockIdx.x * blockDim.x + threadIdx.x) >> 5;
    int lane = threadIdx.x & 31;
    if (gw >= G) return;
    float s = g_psum[gw * 64 + lane] * Wlin[lane]
            + g_psum[gw * 64 + 32 + lane] * Wlin[32 + lane];
    #pragma unroll
    for (int o = 16; o; o >>= 1) s += __shfl_down_sync(0xffffffffu, s, o);
    if (lane == 0) out[gw] = s / fmaxf(g_pcnt[gw], 1.f) + blin[0];
}

extern "C" void kernel_launch(void* const* d_in, const int* in_sizes, int n_in,
                              void* d_out, int out_size) {
    const float* x     = (const float*)d_in[0];
    const float* pos   = (const float*)d_in[1];
    const void*  eidx  = d_in[2];
    const void*  batch = d_in[3];
    const float* W1a = (const float*)d_in[4];
    const float* b1a = (const float*)d_in[5];
    const float* W1b = (const float*)d_in[6];
    const float* b1b = (const float*)d_in[7];
    const float* W2a = (const float*)d_in[8];
    const float* b2a = (const float*)d_in[9];
    const float* W2b = (const float*)d_in[10];
    const float* b2b = (const float*)d_in[11];
    const float* Wlin = (const float*)d_in[12];
    const float* blin = (const float*)d_in[13];
    float* out = (float*)d_out;

    int n = in_sizes[3];
    int E = in_sizes[2] / 2;
    int G = out_size;

    detect_kernel<<<1, 32>>>((const unsigned int*)eidx, E);

    int initN = n * 64 > E ? n * 64 : E;
    init_kernel<<<(initN + 255) / 256, 256>>>(x, pos, eidx, batch, n, E, G);

    pool_count<<<(n + 255) / 256, 256>>>(n);

    // conv1: scatter h0 into z1 (4 float4 chunks/row)
    scatter_kernel<2, true><<<(E * 4 + 255) / 256, 256>>>(E);

    // conv1 MLP: z1[n,16] -> h1
    mlp_kernel<16, 1><<<(n + 127) / 128, 128>>>(W1a, b1a, W1b, b1b, 14, n);

    // conv2: scatter h1 into z2 (16 float4 chunks/row)
    scatter_kernel<4, false><<<(E * 16 + 255) / 256, 256>>>(E);

    // conv2 MLP: (h1+z2)[n,64] -> relu -> pooled sums (fused)
    mlp_kernel<64, 2><<<(n + 127) / 128, 128>>>(W2a, b2a, W2b, b2b, 64, n);

    final_kernel<<<(G * 32 + 255) / 256, 256>>>(Wlin, blin, out, G);
}